// round 5
// baseline (speedup 1.0000x reference)
#include <cuda_runtime.h>
#include <cuda_bf16.h>
#include <math.h>
#include <cfloat>
#include <cstdint>

// ===========================================================================
// MIL-NCE head: s = (v @ t^T)/0.1, N=4096, T=4, D=256 (NT=16384)
// Outputs: [loss, recall1, recall5, recall10, avg_rank]
//
// Fully fused: no S materialization.
//  K0 init   : rank counters <- 0
//  K1 split  : fp32 -> 2x bf16 splits of v and t
//  K2 pos    : exact fp32 positives p[i][t] = (v_i . t_{4i+t}) * 10
//  K3 gemm   : mma.sync bf16 3-product GEMM; epilogue computes rank counts
//              (vs positives, self-excluded), per-warp-tile row/col
//              (max, sumexp) partials. Nothing else leaves the CTA.
//  K4 rowfin : warp-per-row deterministic merge of partials -> loss+metrics
//  K5 reduce : deterministic means
// ===========================================================================

namespace {
constexpr int N  = 4096;
constexpr int T  = 4;
constexpr int NT = 16384;
constexpr int D  = 256;
constexpr float SCALE   = 10.0f;
constexpr float LSE_CUT = 30.0f;

constexpr int BM = 128, BN = 128;
constexpr int KC = 64;                      // K chunk: 64 bf16 = 128B rows (SW128)
constexpr int NCHUNK = D / KC;              // 4
constexpr int CTILE = NT / BN;              // 128 col tiles
constexpr int RTILE = N / BM;               // 32 row tiles
constexpr int CSLOT = CTILE * 2;            // 256 row-LSE slots (per 64-col warp tile)
constexpr int RSLOT = RTILE * 4;            // 128 col-LSE slots (per 32-row warp tile)

constexpr int NA = N * D;
constexpr int NB = NT * D;

constexpr int TILE_B    = BM * KC * 2;      // 16384 bytes per split tile
constexpr int STAGE_B   = 4 * TILE_B;       // A0,A1,B0,B1 = 65536
constexpr int GEMM_SMEM = 2 * STAGE_B;      // 131072 (double buffer)
}

// ------------------------- device scratch ---------------------------------
__device__ __nv_bfloat16  g_As[2][NA];
__device__ __nv_bfloat16  g_Bs[2][NB];
__device__ float4         g_pos[N];              // positives (scaled)
__device__ int            g_cnt[N][T];
__device__ float2         g_rowMS[N][CSLOT];     // (max, sumexp) per row slot, 8MB
__device__ float2         g_colMS[NT][RSLOT];    // (max, sumexp) per col slot, 16MB
__device__ float          g_rowout[N][5];

// ------------------------- helpers ----------------------------------------
__device__ __forceinline__ uint32_t smem_u32(const void* p) {
    uint32_t a;
    asm("{ .reg .u64 t; cvta.to.shared.u64 t, %1; cvt.u32.u64 %0, t; }" : "=r"(a) : "l"(p));
    return a;
}
__device__ __forceinline__ uint32_t sw128(uint32_t b) { return b ^ ((b >> 3) & 0x70); }

__device__ __forceinline__ void ldsm4(uint32_t* r, uint32_t addr) {
    asm volatile("ldmatrix.sync.aligned.m8n8.x4.shared.b16 {%0,%1,%2,%3}, [%4];"
        : "=r"(r[0]), "=r"(r[1]), "=r"(r[2]), "=r"(r[3]) : "r"(addr));
}
__device__ __forceinline__ void mma_bf16(float* d, const uint32_t* a, uint32_t b0, uint32_t b1) {
    asm volatile("mma.sync.aligned.m16n8k16.row.col.f32.bf16.bf16.f32 "
        "{%0,%1,%2,%3}, {%4,%5,%6,%7}, {%8,%9}, {%0,%1,%2,%3};"
        : "+f"(d[0]), "+f"(d[1]), "+f"(d[2]), "+f"(d[3])
        : "r"(a[0]), "r"(a[1]), "r"(a[2]), "r"(a[3]), "r"(b0), "r"(b1));
}
__device__ __forceinline__ void cp16(uint32_t dst, const void* src) {
    asm volatile("cp.async.cg.shared.global [%0], [%1], 16;" :: "r"(dst), "l"(src));
}
#define CP_COMMIT() asm volatile("cp.async.commit_group;" ::: "memory")
#define CP_WAIT(n)  asm volatile("cp.async.wait_group %0;" :: "n"(n) : "memory")

// (m,s) logsumexp-pair merge, deterministic given fixed call order
__device__ __forceinline__ void msmerge(float& m, float& s, float m2, float s2) {
    float M = fmaxf(m, m2);
    s = s * expf(m - M) + s2 * expf(m2 - M);
    m = M;
}

// ===========================================================================
// K0: init rank counters
__global__ void init_kernel() {
    int i = blockIdx.x * 256 + threadIdx.x;
    if (i < NT) g_cnt[i >> 2][i & 3] = 0;
}

// ===========================================================================
// K1: 2-way bf16 split
__global__ __launch_bounds__(256)
void split_kernel(const float* __restrict__ v, const float* __restrict__ t) {
    int i = blockIdx.x * 256 + threadIdx.x;
    if (i >= NA + NB) return;
    float a = (i < NA) ? v[i] : t[i - NA];
    __nv_bfloat16 h0 = __float2bfloat16(a);
    float r1 = a - __bfloat162float(h0);
    __nv_bfloat16 h1 = __float2bfloat16(r1);
    if (i < NA) { g_As[0][i] = h0; g_As[1][i] = h1; }
    else { int j = i - NA; g_Bs[0][j] = h0; g_Bs[1][j] = h1; }
}

// ===========================================================================
// K2: exact fp32 positives. One warp per (i,t) pair.
__global__ __launch_bounds__(256)
void pos_kernel(const float* __restrict__ v, const float* __restrict__ t) {
    int w = (blockIdx.x * 256 + threadIdx.x) >> 5;   // 0..16383
    int lane = threadIdx.x & 31;
    int i = w >> 2, tt = w & 3;
    const float4* vp = reinterpret_cast<const float4*>(v + (size_t)i * D);
    const float4* tp = reinterpret_cast<const float4*>(t + (size_t)w * D);
    float s = 0.f;
    #pragma unroll
    for (int k = 0; k < 2; k++) {
        float4 a = vp[lane + 32 * k];
        float4 b = tp[lane + 32 * k];
        s += a.x * b.x + a.y * b.y + a.z * b.z + a.w * b.w;
    }
    #pragma unroll
    for (int off = 16; off; off >>= 1)
        s += __shfl_xor_sync(0xffffffffu, s, off);
    if (lane == 0) reinterpret_cast<float*>(&g_pos[i])[tt] = s * SCALE;
}

// ===========================================================================
// K3: HMMA GEMM + fused epilogue (no S output).
// Block tile 128x128, 8 warps as 4(m) x 2(n): warp tile 32x64.
__global__ __launch_bounds__(256, 1)
void gemm_mma() {
    extern __shared__ char smem[];
    __shared__ float4 spos[BM];               // positives for this CTA's rows
    const uint32_t sb = smem_u32(smem);
    const int tid = threadIdx.x, lane = tid & 31, wid = tid >> 5;
    const int wm = wid >> 1, wn = wid & 1;
    const int bn = blockIdx.x, bm = blockIdx.y;

    if (tid < BM) spos[tid] = g_pos[bm * BM + tid];

    // ldmatrix per-lane addressing (SW128, 128B rows)
    const int a_r    = lane & 15;
    const int a_koff = (lane >> 4) * 16;
    const int b_r    = (lane & 7) + ((lane & 16) >> 1);
    const int b_koff = (lane & 8) << 1;
    const uint32_t a_xm = (uint32_t)(a_r & 7) << 4;
    const uint32_t b_xm = (uint32_t)(b_r & 7) << 4;

    uint32_t a_rowb[2], b_rowb[4];
    #pragma unroll
    for (int mi = 0; mi < 2; mi++) a_rowb[mi] = (uint32_t)(wm * 32 + mi * 16 + a_r) * 128;
    #pragma unroll
    for (int p = 0; p < 4; p++)    b_rowb[p]  = (uint32_t)(wn * 64 + p * 16 + b_r) * 128;

    float acc[2][8][4];
    #pragma unroll
    for (int mi = 0; mi < 2; mi++)
        #pragma unroll
        for (int nf = 0; nf < 8; nf++)
            #pragma unroll
            for (int q = 0; q < 4; q++) acc[mi][nf][q] = 0.f;

    auto prefetch = [&](int stage, int kc) {
        const int k0 = kc * KC;
        #pragma unroll
        for (int i = 0; i < 16; i++) {
            int g = i * 256 + tid;
            int s = g >> 10;
            int idx = g & 1023;
            int r = idx >> 3, b = idx & 7;
            const __nv_bfloat16* src =
                (s < 2) ? (g_As[s]     + (size_t)(bm * BM + r) * D + k0 + b * 8)
                        : (g_Bs[s - 2] + (size_t)(bn * BN + r) * D + k0 + b * 8);
            cp16(sb + stage * STAGE_B + s * TILE_B + sw128(r * 128 + b * 16), src);
        }
    };

    prefetch(0, 0);
    CP_COMMIT();

    for (int kc = 0; kc < NCHUNK; kc++) {
        if (kc < NCHUNK - 1) { prefetch((kc + 1) & 1, kc + 1); CP_COMMIT(); CP_WAIT(1); }
        else { CP_WAIT(0); }
        __syncthreads();

        const uint32_t base = sb + (kc & 1) * STAGE_B;
        #pragma unroll
        for (int k16 = 0; k16 < 4; k16++) {
            const uint32_t kb = k16 * 32;
            uint32_t afr[2][2][4];
            #pragma unroll
            for (int s2 = 0; s2 < 2; s2++)
                #pragma unroll
                for (int mi = 0; mi < 2; mi++)
                    ldsm4(afr[s2][mi], base + s2 * TILE_B + a_rowb[mi] + ((kb + a_koff) ^ a_xm));
            uint32_t bfr[2][4][4];
            #pragma unroll
            for (int s2 = 0; s2 < 2; s2++)
                #pragma unroll
                for (int p = 0; p < 4; p++)
                    ldsm4(bfr[s2][p], base + (2 + s2) * TILE_B + b_rowb[p] + ((kb + b_koff) ^ b_xm));

            #pragma unroll
            for (int mi = 0; mi < 2; mi++)
                #pragma unroll
                for (int nf = 0; nf < 8; nf++) {
                    const uint32_t* bp0 = &bfr[0][nf >> 1][(nf & 1) * 2];
                    const uint32_t* bp1 = &bfr[1][nf >> 1][(nf & 1) * 2];
                    mma_bf16(acc[mi][nf], afr[0][mi], bp0[0], bp0[1]);
                    mma_bf16(acc[mi][nf], afr[0][mi], bp1[0], bp1[1]);
                    mma_bf16(acc[mi][nf], afr[1][mi], bp0[0], bp0[1]);
                }
        }
        __syncthreads();
    }

    // ======== fused epilogue ========
    #pragma unroll
    for (int mi = 0; mi < 2; mi++)
        #pragma unroll
        for (int nf = 0; nf < 8; nf++)
            #pragma unroll
            for (int q = 0; q < 4; q++) acc[mi][nf][q] *= SCALE;

    const int qr = lane >> 2;
    const int qc = (lane & 3) * 2;
    const int gcolbase = bn * BN + wn * 64;

    // --- per-row: rank counts (self-excluded) + row-tile (max, sumexp) ---
    #pragma unroll
    for (int mi = 0; mi < 2; mi++)
        #pragma unroll
        for (int h = 0; h < 2; h++) {
            const int lrow = wm * 32 + mi * 16 + h * 8 + qr;
            const int grow = bm * BM + lrow;
            const float4 pv = spos[lrow];
            int c0 = 0, c1 = 0, c2 = 0, c3 = 0;
            float m = -FLT_MAX;
            #pragma unroll
            for (int nf = 0; nf < 8; nf++)
                #pragma unroll
                for (int b = 0; b < 2; b++) {
                    const float x = acc[mi][nf][2 * h + b];
                    const int gcol = gcolbase + nf * 8 + qc + b;
                    const bool sv = (gcol >> 2) == grow;
                    c0 += (x > pv.x) && !(sv && (gcol & 3) == 0);
                    c1 += (x > pv.y) && !(sv && (gcol & 3) == 1);
                    c2 += (x > pv.z) && !(sv && (gcol & 3) == 2);
                    c3 += (x > pv.w) && !(sv && (gcol & 3) == 3);
                    m = fmaxf(m, x);
                }
            #pragma unroll
            for (int off = 1; off <= 2; off <<= 1) {
                c0 += __shfl_xor_sync(0xffffffffu, c0, off);
                c1 += __shfl_xor_sync(0xffffffffu, c1, off);
                c2 += __shfl_xor_sync(0xffffffffu, c2, off);
                c3 += __shfl_xor_sync(0xffffffffu, c3, off);
                m = fmaxf(m, __shfl_xor_sync(0xffffffffu, m, off));
            }
            const float thr = m - LSE_CUT;
            float s = 0.f;
            #pragma unroll
            for (int nf = 0; nf < 8; nf++)
                #pragma unroll
                for (int b = 0; b < 2; b++) {
                    const float x = acc[mi][nf][2 * h + b];
                    if (x > thr) s += expf(x - m);
                }
            s += __shfl_xor_sync(0xffffffffu, s, 1);
            s += __shfl_xor_sync(0xffffffffu, s, 2);
            if ((lane & 3) == 0) {
                atomicAdd(&g_cnt[grow][0], c0);
                atomicAdd(&g_cnt[grow][1], c1);
                atomicAdd(&g_cnt[grow][2], c2);
                atomicAdd(&g_cnt[grow][3], c3);
                g_rowMS[grow][bn * 2 + wn] = make_float2(m, s);
            }
        }

    // --- per-col: col-tile (max, sumexp) ---
    #pragma unroll
    for (int nf = 0; nf < 8; nf++)
        #pragma unroll
        for (int b = 0; b < 2; b++) {
            float m = -FLT_MAX;
            #pragma unroll
            for (int mi = 0; mi < 2; mi++)
                #pragma unroll
                for (int h = 0; h < 2; h++)
                    m = fmaxf(m, acc[mi][nf][2 * h + b]);
            #pragma unroll
            for (int off = 4; off <= 16; off <<= 1)
                m = fmaxf(m, __shfl_xor_sync(0xffffffffu, m, off));
            const float thr = m - LSE_CUT;
            float s = 0.f;
            #pragma unroll
            for (int mi = 0; mi < 2; mi++)
                #pragma unroll
                for (int h = 0; h < 2; h++) {
                    const float x = acc[mi][nf][2 * h + b];
                    if (x > thr) s += expf(x - m);
                }
            #pragma unroll
            for (int off = 4; off <= 16; off <<= 1)
                s += __shfl_xor_sync(0xffffffffu, s, off);
            if (lane < 4)
                g_colMS[gcolbase + nf * 8 + qc + b][bm * 4 + wm] = make_float2(m, s);
        }
}

// ===========================================================================
// K4: warp-per-row deterministic merge -> loss + metrics per row
__global__ __launch_bounds__(256)
void rowfin_kernel() {
    const int i = blockIdx.x * 8 + (threadIdx.x >> 5);   // row
    const int lane = threadIdx.x & 31;

    // seed from first slot, then strided merges (fixed order)
    float2 e = g_rowMS[i][lane];
    float m = e.x, s = e.y;
    for (int k = lane + 32; k < CSLOT; k += 32) {
        float2 f = g_rowMS[i][k];
        msmerge(m, s, f.x, f.y);
    }
    #pragma unroll
    for (int t = 0; t < 4; t++)
        for (int k = lane; k < RSLOT; k += 32) {
            float2 f = g_colMS[i * 4 + t][k];
            msmerge(m, s, f.x, f.y);
        }
    #pragma unroll
    for (int off = 16; off; off >>= 1) {
        float m2 = __shfl_xor_sync(0xffffffffu, m, off);
        float s2 = __shfl_xor_sync(0xffffffffu, s, off);
        msmerge(m, s, m2, s2);
    }

    if (lane == 0) {
        float denom = m + logf(s);
        float4 p = g_pos[i];
        float pm = fmaxf(fmaxf(p.x, p.y), fmaxf(p.z, p.w));
        float nom = pm + logf(expf(p.x - pm) + expf(p.y - pm) +
                              expf(p.z - pm) + expf(p.w - pm));
        float r1 = 0.f, r5 = 0.f, r10 = 0.f, ar = 0.f;
        #pragma unroll
        for (int t = 0; t < 4; t++) {
            int rk = g_cnt[i][t];
            r1  += (rk < 1);
            r5  += (rk < 5);
            r10 += (rk < 10);
            ar  += (float)rk;
        }
        g_rowout[i][0] = denom - nom;
        g_rowout[i][1] = r1  * 0.25f;
        g_rowout[i][2] = r5  * 0.25f;
        g_rowout[i][3] = r10 * 0.25f;
        g_rowout[i][4] = ar  * 0.25f;
    }
}

// ===========================================================================
// K5: deterministic means
__global__ __launch_bounds__(256)
void final_kernel(float* __restrict__ out) {
    __shared__ double sacc[5][256];
    int tid = threadIdx.x;
    double a[5] = {0, 0, 0, 0, 0};
    for (int i = tid; i < N; i += 256)
        #pragma unroll
        for (int q = 0; q < 5; q++) a[q] += (double)g_rowout[i][q];
    #pragma unroll
    for (int q = 0; q < 5; q++) sacc[q][tid] = a[q];
    __syncthreads();
    for (int off = 128; off > 0; off >>= 1) {
        if (tid < off)
            #pragma unroll
            for (int q = 0; q < 5; q++) sacc[q][tid] += sacc[q][tid + off];
        __syncthreads();
    }
    if (tid == 0)
        #pragma unroll
        for (int q = 0; q < 5; q++) out[q] = (float)(sacc[q][0] / (double)N);
}

// ===========================================================================
extern "C" void kernel_launch(void* const* d_in, const int* in_sizes, int n_in,
                              void* d_out, int out_size) {
    const float* v = (const float*)d_in[0];   // [4096, 256]
    const float* t = (const float*)d_in[1];   // [16384, 256]
    (void)in_sizes; (void)n_in; (void)out_size;

    static int attr_done = 0;
    if (!attr_done) {
        cudaFuncSetAttribute(gemm_mma, cudaFuncAttributeMaxDynamicSharedMemorySize, GEMM_SMEM);
        attr_done = 1;
    }

    init_kernel<<<NT / 256, 256>>>();
    split_kernel<<<(NA + NB + 255) / 256, 256>>>(v, t);
    pos_kernel<<<(NT * 32) / 256, 256>>>(v, t);
    gemm_mma<<<dim3(CTILE, RTILE), 256, GEMM_SMEM>>>();
    rowfin_kernel<<<N / 8, 256>>>();
    final_kernel<<<1, 256>>>((float*)d_out);
}